// round 16
// baseline (speedup 1.0000x reference)
#include <cuda_runtime.h>
#include <cuda_fp16.h>
#include <math.h>
#include <stdint.h>

// Problem constants
#define TOKS 4096      // B*S = 2*2048
#define SEQ  2048
#define NB   2
#define NH   16
#define HD   128
#define HIDN 2048
#define DLAT 512

// fp32 scratch (GEMM outputs pre-norm)
__device__ float g_q[TOKS * 2048];
__device__ float g_k[TOKS * 2048];

// fp16 scratch
__device__ __half h_x[TOKS * HIDN];
__device__ __half h_Wq[HIDN * 2048];
__device__ __half h_Wkv[HIDN * DLAT];
__device__ __half h_Wkrn[DLAT * 2048];   // combined head-interleaved kr|kn weight
__device__ __half h_Wv[DLAT * 2048];
__device__ __half h_Wo[2048 * HIDN];
__device__ __half h_lat[TOKS * DLAT];
__device__ __half h_attn[TOKS * 2048];
__device__ __half h_q[TOKS * 2048];   // [b][h][s][d], unswizzled, *log2e/sqrt(D)
__device__ __half h_k[TOKS * 2048];   // [b][h][s][d], XOR-swizzled rows
__device__ __half h_v[TOKS * 2048];   // [b][h][s][d], XOR-swizzled rows

// ----------------------------------------------------------------------------
// Fused fp32->fp16 conversion of x + all weights (Wkr/Wkn remap into h_Wkrn).
// ----------------------------------------------------------------------------
#define V4_X    2097152L
#define V4_WQ   1048576L
#define V4_WKV   262144L
#define V4_WKR   131072L
#define V4_WKN   131072L
#define V4_WV    262144L
#define V4_WO   1048576L
#define CV_B0 (V4_X)
#define CV_B1 (CV_B0 + V4_WQ)
#define CV_B2 (CV_B1 + V4_WKV)
#define CV_B3 (CV_B2 + V4_WKR)
#define CV_B4 (CV_B3 + V4_WKN)
#define CV_B5 (CV_B4 + V4_WV)
#define CV_B6 (CV_B5 + V4_WO)
#define CV_BLOCKS (CV_B6 / 256)

__device__ __forceinline__ void cvt4(const float* s, __half* d, long si, long di)
{
    float4 v = *(const float4*)(s + si * 4);
    *(__half2*)(d + di * 4)     = __floats2half2_rn(v.x, v.y);
    *(__half2*)(d + di * 4 + 2) = __floats2half2_rn(v.z, v.w);
}

__global__ __launch_bounds__(256)
void convert_all(const float* __restrict__ x,  const float* __restrict__ Wq,
                 const float* __restrict__ Wkv, const float* __restrict__ Wkr,
                 const float* __restrict__ Wkn, const float* __restrict__ Wv,
                 const float* __restrict__ Wo,
                 __half* __restrict__ hx,  __half* __restrict__ hWq,
                 __half* __restrict__ hWkv, __half* __restrict__ hWkrn,
                 __half* __restrict__ hWv, __half* __restrict__ hWo)
{
    long v4 = (long)blockIdx.x * 256 + threadIdx.x;
    if (v4 < CV_B0)      cvt4(x,   hx,   v4, v4);
    else if (v4 < CV_B1) cvt4(Wq,  hWq,  v4 - CV_B0, v4 - CV_B0);
    else if (v4 < CV_B2) cvt4(Wkv, hWkv, v4 - CV_B1, v4 - CV_B1);
    else if (v4 < CV_B3) {
        long e = v4 - CV_B2;
        long row = e >> 8;
        int j = (int)(e & 255) * 4;
        int h = j >> 6, c = j & 63;
        long dst = row * 2048 + h * 128 + c;
        cvt4(Wkr, hWkrn, e, dst >> 2);
    } else if (v4 < CV_B4) {
        long e = v4 - CV_B3;
        long row = e >> 8;
        int j = (int)(e & 255) * 4;
        int h = j >> 6, c = j & 63;
        long dst = row * 2048 + h * 128 + 64 + c;
        cvt4(Wkn, hWkrn, e, dst >> 2);
    }
    else if (v4 < CV_B5) cvt4(Wv, hWv, v4 - CV_B4, v4 - CV_B4);
    else                 cvt4(Wo, hWo, v4 - CV_B5, v4 - CV_B5);
}

// ----------------------------------------------------------------------------
#define AS_STRIDE 40
#define BS_STRIDE 136
#define A_STG (128 * AS_STRIDE)
#define B_STG (32 * BS_STRIDE)

__device__ __forceinline__ uint32_t sptr(const void* p)
{
    return (uint32_t)__cvta_generic_to_shared(p);
}
__device__ __forceinline__ void ldsm_x4(uint32_t* r, uint32_t addr)
{
    asm volatile("ldmatrix.sync.aligned.m8n8.x4.shared.b16 {%0,%1,%2,%3}, [%4];\n"
                 : "=r"(r[0]), "=r"(r[1]), "=r"(r[2]), "=r"(r[3]) : "r"(addr));
}
__device__ __forceinline__ void ldsm_x2t(uint32_t* r, uint32_t addr)
{
    asm volatile("ldmatrix.sync.aligned.m8n8.x2.trans.shared.b16 {%0,%1}, [%2];\n"
                 : "=r"(r[0]), "=r"(r[1]) : "r"(addr));
}
__device__ __forceinline__ void ldsm_x4t(uint32_t* r, uint32_t addr)
{
    asm volatile("ldmatrix.sync.aligned.m8n8.x4.trans.shared.b16 {%0,%1,%2,%3}, [%4];\n"
                 : "=r"(r[0]), "=r"(r[1]), "=r"(r[2]), "=r"(r[3]) : "r"(addr));
}
__device__ __forceinline__ void mma16816(float* c, const uint32_t* a, const uint32_t* b)
{
    asm volatile(
        "mma.sync.aligned.m16n8k16.row.col.f32.f16.f16.f32 "
        "{%0,%1,%2,%3}, {%4,%5,%6,%7}, {%8,%9}, {%0,%1,%2,%3};\n"
        : "+f"(c[0]), "+f"(c[1]), "+f"(c[2]), "+f"(c[3])
        : "r"(a[0]), "r"(a[1]), "r"(a[2]), "r"(a[3]), "r"(b[0]), "r"(b[1]));
}
__device__ __forceinline__ void cp16(uint32_t saddr, const void* g)
{
    asm volatile("cp.async.cg.shared.global [%0], [%1], 16;\n" :: "r"(saddr), "l"(g));
}
__device__ __forceinline__ void cp_commit()
{
    asm volatile("cp.async.commit_group;\n");
}
template <int N>
__device__ __forceinline__ void cp_wait()
{
    asm volatile("cp.async.wait_group %0;\n" :: "n"(N));
}
__device__ __forceinline__ float fast_ex2(float x)
{
    float y;
    asm("ex2.approx.ftz.f32 %0, %1;\n" : "=f"(y) : "f"(x));
    return y;
}
// mbarrier helpers
__device__ __forceinline__ void mbar_init(uint32_t addr, uint32_t count)
{
    asm volatile("mbarrier.init.shared.b64 [%0], %1;\n" :: "r"(addr), "r"(count) : "memory");
}
__device__ __forceinline__ void mbar_expect_tx(uint32_t addr, uint32_t bytes)
{
    asm volatile("mbarrier.arrive.expect_tx.shared.b64 _, [%0], %1;\n"
                 :: "r"(addr), "r"(bytes) : "memory");
}
__device__ __forceinline__ void mbar_arrive(uint32_t addr)
{
    asm volatile("mbarrier.arrive.release.cta.shared::cta.b64 _, [%0];\n"
                 :: "r"(addr) : "memory");
}
__device__ __forceinline__ void mbar_wait(uint32_t addr, uint32_t parity)
{
    asm volatile(
        "{\n\t.reg .pred P;\n"
        "WAIT_%=:\n\t"
        "mbarrier.try_wait.parity.acquire.cta.shared::cta.b64 P, [%0], %1;\n\t"
        "@!P bra WAIT_%=;\n\t}"
        :: "r"(addr), "r"(parity) : "memory");
}
__device__ __forceinline__ void bulk_g2s(uint32_t dst, const void* src, uint32_t bytes,
                                         uint32_t mbar)
{
    asm volatile(
        "cp.async.bulk.shared::cta.global.mbarrier::complete_tx::bytes [%0], [%1], %2, [%3];\n"
        :: "r"(dst), "l"(src), "r"(bytes), "r"(mbar) : "memory");
}

// ----------------------------------------------------------------------------
// Tensor-core GEMM. SWZV: store fp16 output in [b][h][s][d] XOR-swizzled.
// ----------------------------------------------------------------------------
template <typename T, bool SWZV>
__global__ __launch_bounds__(256, 2)
void hgemm128(const __half* __restrict__ A, const __half* __restrict__ B,
              T* __restrict__ C, int M, int N, int K,
              int lgGroup, int outstride, int base, int ldc)
{
    __shared__ __half Asb[2 * A_STG];
    __shared__ __half Bsb[2 * B_STG];

    const int tid  = threadIdx.x;
    const int warp = tid >> 5;
    const int lane = tid & 31;
    const int bm = blockIdx.y * 128;
    const int bn = blockIdx.x * 128;
    const int wm = (warp & 1) * 64;
    const int wn = (warp >> 1) * 32;

    float c[4][4][4];
#pragma unroll
    for (int mt = 0; mt < 4; ++mt)
#pragma unroll
        for (int nt = 0; nt < 4; ++nt)
#pragma unroll
            for (int i = 0; i < 4; ++i) c[mt][nt][i] = 0.0f;

    const int arow0 = tid >> 2,  akc = (tid & 3) * 8;
    const int brow0 = tid >> 4,  bnc = (tid & 15) * 8;

    const uint32_t a_base = sptr(&Asb[(wm + (lane & 15)) * AS_STRIDE + (lane >> 4) * 8]);
    const uint32_t b_base = sptr(&Bsb[(lane & 15) * BS_STRIDE + wn]);

    const int nk = K >> 5;

#define GEMM_LOAD_STAGE(s, k0)                                                        \
    do {                                                                              \
        cp16(sptr(&Asb[(s) * A_STG + arow0 * AS_STRIDE + akc]),                       \
             A + (size_t)(bm + arow0) * K + (k0) + akc);                              \
        cp16(sptr(&Asb[(s) * A_STG + (arow0 + 64) * AS_STRIDE + akc]),                \
             A + (size_t)(bm + arow0 + 64) * K + (k0) + akc);                         \
        cp16(sptr(&Bsb[(s) * B_STG + brow0 * BS_STRIDE + bnc]),                       \
             B + (size_t)((k0) + brow0) * N + bn + bnc);                              \
        cp16(sptr(&Bsb[(s) * B_STG + (brow0 + 16) * BS_STRIDE + bnc]),                \
             B + (size_t)((k0) + brow0 + 16) * N + bn + bnc);                         \
    } while (0)

    GEMM_LOAD_STAGE(0, 0);
    cp_commit();

    for (int t = 0; t < nk; ++t) {
        cp_wait<0>();
        __syncthreads();
        if (t + 1 < nk) {
            GEMM_LOAD_STAGE((t + 1) & 1, (t + 1) << 5);
            cp_commit();
        }

        const uint32_t ab = a_base + (t & 1) * A_STG * 2;
        const uint32_t bb = b_base + (t & 1) * B_STG * 2;
#pragma unroll
        for (int kt = 0; kt < 2; ++kt) {
            uint32_t a[4][4], b[4][2];
#pragma unroll
            for (int mt = 0; mt < 4; ++mt)
                ldsm_x4(a[mt], ab + (mt * 16 * AS_STRIDE + kt * 16) * 2);
#pragma unroll
            for (int nt = 0; nt < 4; ++nt)
                ldsm_x2t(b[nt], bb + (kt * 16 * BS_STRIDE + nt * 8) * 2);
#pragma unroll
            for (int mt = 0; mt < 4; ++mt)
#pragma unroll
                for (int nt = 0; nt < 4; ++nt)
                    mma16816(c[mt][nt], a[mt], b[nt]);
        }
    }

    const int gmask = (1 << lgGroup) - 1;
    const int gid = lane >> 2;
    const int tig = lane & 3;
#pragma unroll
    for (int mt = 0; mt < 4; ++mt) {
#pragma unroll
        for (int nt = 0; nt < 4; ++nt) {
            int col = bn + wn + nt * 8 + tig * 2;
            int oc = ((col >> lgGroup) * outstride) + base + (col & gmask);
            int r0 = bm + wm + mt * 16 + gid;
            if (sizeof(T) == 4) {
                *(float2*)&((float*)C)[(size_t)r0 * ldc + oc] =
                    make_float2(c[mt][nt][0], c[mt][nt][1]);
                *(float2*)&((float*)C)[(size_t)(r0 + 8) * ldc + oc] =
                    make_float2(c[mt][nt][2], c[mt][nt][3]);
            } else if (SWZV) {
                int hh = oc >> 7, d = oc & 127;
#pragma unroll
                for (int rr = 0; rr < 2; ++rr) {
                    int tok = r0 + rr * 8;
                    int bb2 = tok >> 11, ss = tok & 2047;
                    size_t rb = ((size_t)(bb2 * 16 + hh) * 2048 + ss) * 128;
                    int dd = (((d >> 3) ^ (ss & 7)) << 3) + (d & 7);
                    *(__half2*)&((__half*)C)[rb + dd] =
                        __floats2half2_rn(c[mt][nt][rr * 2], c[mt][nt][rr * 2 + 1]);
                }
            } else {
                *(__half2*)&((__half*)C)[(size_t)r0 * ldc + oc] =
                    __floats2half2_rn(c[mt][nt][0], c[mt][nt][1]);
                *(__half2*)&((__half*)C)[(size_t)(r0 + 8) * ldc + oc] =
                    __floats2half2_rn(c[mt][nt][2], c[mt][nt][3]);
            }
        }
    }
}

// ----------------------------------------------------------------------------
// RMSNorm + fp16 repack -> [b][h][s][d]; swz applies 16B-chunk XOR (for K).
// ----------------------------------------------------------------------------
__global__ __launch_bounds__(256)
void rmsnorm_h(const float* __restrict__ in, const float* __restrict__ g,
               __half* __restrict__ out, float pscale, int swz)
{
    int row = blockIdx.x * 8 + (threadIdx.x >> 5);   // row = tok*16 + h
    int lane = threadIdx.x & 31;
    float4 v = *((const float4*)(in + (size_t)row * 128) + lane);
    float ss = v.x * v.x + v.y * v.y + v.z * v.z + v.w * v.w;
#pragma unroll
    for (int o = 16; o; o >>= 1) ss += __shfl_xor_sync(0xffffffffu, ss, o);
    float r = rsqrtf(ss * (1.0f / 128.0f) + 1e-6f) * pscale;
    float4 gv = ((const float4*)g)[lane];
    int tok = row >> 4, h = row & 15;
    int b = tok >> 11, s = tok & 2047;
    int xs = swz ? (s & 7) : 0;
    int dd = (((lane >> 1) ^ xs) << 3) + (lane & 1) * 4;
    __half* dst = out + ((size_t)(b * 16 + h) * 2048 + s) * 128 + dd;
    *(__half2*)dst       = __floats2half2_rn(v.x * r * gv.x, v.y * r * gv.y);
    *(__half2*)(dst + 2) = __floats2half2_rn(v.z * r * gv.z, v.w * r * gv.w);
}

// ----------------------------------------------------------------------------
// Tensor-core causal flash attention: 32-key tiles, double-buffered combined
// K+V stages (bulk copies), WARP-DECOUPLED pipeline: no per-tile syncthreads;
// per-stage "free" mbarriers (arrive count 4) gate buffer reuse, so warps can
// drift up to a full tile apart. Fixed-shift MUFU softmax.
// 128 threads / 64 q-rows / 3 CTAs-SM.
// ----------------------------------------------------------------------------
#define SOFTMAX_SHIFT 2.8853900817779268f   /* 2*log2e */
#define STG_BYTES 16384u          // K 8KB + V 8KB per stage
#define KTILE_B 8192u

__global__ __launch_bounds__(128, 3)
void attn_mma(const __half* __restrict__ q, const __half* __restrict__ k,
              const __half* __restrict__ v, __half* __restrict__ o)
{
    __shared__ __align__(128) __half KV[2][8192];          // 2 stages x 16KB
    __shared__ __align__(8) unsigned long long mbar[4];    // full0 full1 free0 free1

    const int bh = blockIdx.y;
    const int b = bh >> 4, h = bh & 15;
    const int qb = ((int)gridDim.x - 1 - (int)blockIdx.x) * 64;   // heavy first
    const int tid = threadIdx.x;
    const int lane = tid & 31;
    const int warp = tid >> 5;
    const size_t base = (size_t)bh * SEQ * HD;
    const int r0 = warp * 16 + (lane >> 2);
    const int w0 = qb + warp * 16;
    const int c2 = (lane & 3) * 2;

    const uint32_t mfull = sptr(&mbar[0]);
    const uint32_t mfree = sptr(&mbar[2]);
    const uint32_t smem0 = sptr(KV);

    // Q a-frags
    uint32_t aq[8][4];
    {
        const __half* q0 = q + base + (size_t)(qb + r0) * HD;
#pragma unroll
        for (int kc = 0; kc < 8; ++kc) {
            aq[kc][0] = *(const uint32_t*)(q0 + kc * 16 + c2);
            aq[kc][1] = *(const uint32_t*)(q0 + 8 * HD + kc * 16 + c2);
            aq[kc][2] = *(const uint32_t*)(q0 + kc * 16 + c2 + 8);
            aq[kc][3] = *(const uint32_t*)(q0 + 8 * HD + kc * 16 + c2 + 8);
        }
    }

    float oa[16][4];
#pragma unroll
    for (int nt = 0; nt < 16; ++nt)
#pragma unroll
        for (int i = 0; i < 4; ++i) oa[nt][i] = 0.0f;
    float l0 = 0.0f, l1 = 0.0f;

    // swizzled ldsm lane addressing
    const uint32_t krow = (lane & 7) * 256;
    uint32_t kx[4];
#pragma unroll
    for (int g = 0; g < 4; ++g)
        kx[g] = ((((lane >> 3) + g * 4) ^ (lane & 7)) << 4);
    const uint32_t vrow = (lane & 15) * 256;
    uint32_t vx[8];
#pragma unroll
    for (int ntp = 0; ntp < 8; ++ntp)
        vx[ntp] = ((((lane >> 4) + ntp * 2) ^ (lane & 7)) << 4);

    const __half* kg = k + base;   // 32-key tiles = contiguous 8KB each
    const __half* vg = v + base;
    const int ntiles = qb / 32 + 2;   // keys 0 .. qb+63

    if (tid == 0) {
        mbar_init(mfull, 1);
        mbar_init(mfull + 8, 1);
        mbar_init(mfree, 4);      // one arrive per warp
        mbar_init(mfree + 8, 4);
    }
    __syncthreads();              // the ONLY CTA-wide barrier
    if (tid == 0) {
        mbar_expect_tx(mfull, STG_BYTES);
        bulk_g2s(smem0, kg, KTILE_B, mfull);
        bulk_g2s(smem0 + KTILE_B, vg, KTILE_B, mfull);
        mbar_expect_tx(mfull + 8, STG_BYTES);
        bulk_g2s(smem0 + STG_BYTES, kg + 4096, KTILE_B, mfull + 8);
        bulk_g2s(smem0 + STG_BYTES + KTILE_B, vg + 4096, KTILE_B, mfull + 8);
    }

    for (int t = 0; t < ntiles; ++t) {
        const int j0 = t * 32;
        const int stg = t & 1;
        const uint32_t par = (t >> 1) & 1;
        const uint32_t kbase = smem0 + stg * STG_BYTES;
        const uint32_t vbase = kbase + KTILE_B;

        mbar_wait(mfull + stg * 8, par);

        if (j0 <= w0 + 15) {                       // tile live for this warp
            // S = Q K^T  (32 keys)
            float s[4][4];
#pragma unroll
            for (int nt = 0; nt < 4; ++nt) {
                s[nt][0] = s[nt][1] = s[nt][2] = s[nt][3] = 0.0f;
                uint32_t bk[4][4];
#pragma unroll
                for (int g = 0; g < 4; ++g)
                    ldsm_x4(bk[g], kbase + krow + nt * 2048 + kx[g]);
#pragma unroll
                for (int kc = 0; kc < 8; ++kc)
                    mma16816(s[nt], aq[kc], &bk[kc >> 1][(kc & 1) * 2]);
            }

            if (j0 + 31 > w0) {                    // diagonal masking
#pragma unroll
                for (int nt = 0; nt < 4; ++nt) {
#pragma unroll
                    for (int i = 0; i < 4; ++i) {
                        int col = j0 + nt * 8 + c2 + (i & 1);
                        int rowq = qb + r0 + (i >> 1) * 8;
                        if (col > rowq) s[nt][i] = -1e30f;
                    }
                }
            }

            // fixed-shift MUFU exp2
#pragma unroll
            for (int nt = 0; nt < 4; ++nt) {
                s[nt][0] = fast_ex2(s[nt][0] - SOFTMAX_SHIFT);
                s[nt][1] = fast_ex2(s[nt][1] - SOFTMAX_SHIFT);
                s[nt][2] = fast_ex2(s[nt][2] - SOFTMAX_SHIFT);
                s[nt][3] = fast_ex2(s[nt][3] - SOFTMAX_SHIFT);
                l0 += s[nt][0] + s[nt][1];
                l1 += s[nt][2] + s[nt][3];
            }

            // pack P -> fp16 a-frags
            uint32_t ap[2][4];
#pragma unroll
            for (int kc = 0; kc < 2; ++kc) {
                __half2 t0 = __floats2half2_rn(s[2 * kc][0], s[2 * kc][1]);
                __half2 t1 = __floats2half2_rn(s[2 * kc][2], s[2 * kc][3]);
                __half2 t2 = __floats2half2_rn(s[2 * kc + 1][0], s[2 * kc + 1][1]);
                __half2 t3 = __floats2half2_rn(s[2 * kc + 1][2], s[2 * kc + 1][3]);
                ap[kc][0] = *(uint32_t*)&t0;
                ap[kc][1] = *(uint32_t*)&t1;
                ap[kc][2] = *(uint32_t*)&t2;
                ap[kc][3] = *(uint32_t*)&t3;
            }

            // O += P V
#pragma unroll
            for (int kc = 0; kc < 2; ++kc) {
#pragma unroll
                for (int ntp = 0; ntp < 8; ++ntp) {
                    uint32_t bv[4];
                    ldsm_x4t(bv, vbase + vrow + kc * 4096 + vx[ntp]);
                    mma16816(oa[ntp * 2], ap[kc], &bv[0]);
                    mma16816(oa[ntp * 2 + 1], ap[kc], &bv[2]);
                }
            }
        }

        // this warp is done reading stage stg
        if (lane == 0) mbar_arrive(mfree + stg * 8);

        // producer: refill stage stg for tile t+2 once all 4 warps released it
        if (tid == 0 && t + 2 < ntiles) {
            mbar_wait(mfree + stg * 8, par);
            const __half* kg2 = kg + (size_t)(t + 2) * 4096;
            const __half* vg2 = vg + (size_t)(t + 2) * 4096;
            mbar_expect_tx(mfull + stg * 8, STG_BYTES);
            bulk_g2s(kbase, kg2, KTILE_B, mfull + stg * 8);
            bulk_g2s(vbase, vg2, KTILE_B, mfull + stg * 8);
        }
    }

    // row-sum reduction of l (4 lanes per row), then normalize
    l0 += __shfl_xor_sync(0xffffffffu, l0, 1);
    l0 += __shfl_xor_sync(0xffffffffu, l0, 2);
    l1 += __shfl_xor_sync(0xffffffffu, l1, 1);
    l1 += __shfl_xor_sync(0xffffffffu, l1, 2);
    float inv0 = 1.0f / l0, inv1 = 1.0f / l1;
    size_t tok0 = (size_t)b * SEQ + qb + r0;
    __half* d0 = o + tok0 * 2048 + h * 128 + c2;
    __half* d1 = d0 + (size_t)8 * 2048;
#pragma unroll
    for (int nt = 0; nt < 16; ++nt) {
        *(__half2*)(d0 + nt * 8) = __floats2half2_rn(oa[nt][0] * inv0, oa[nt][1] * inv0);
        *(__half2*)(d1 + nt * 8) = __floats2half2_rn(oa[nt][2] * inv1, oa[nt][3] * inv1);
    }
}

// ----------------------------------------------------------------------------
extern "C" void kernel_launch(void* const* d_in, const int* in_sizes, int n_in,
                              void* d_out, int out_size)
{
    const float* x   = (const float*)d_in[0];
    const float* Wq  = (const float*)d_in[1];
    const float* Wkv = (const float*)d_in[2];
    const float* Wkr = (const float*)d_in[3];
    const float* Wkn = (const float*)d_in[4];
    const float* Wv  = (const float*)d_in[5];
    const float* Wo  = (const float*)d_in[6];
    const float* gq  = (const float*)d_in[7];
    const float* gk  = (const float*)d_in[8];
    float* out = (float*)d_out;

    float *q, *k;
    __half *hx, *hWq, *hWkv, *hWkrn, *hWv, *hWo, *hlat, *hattn, *hq, *hk, *hv;
    cudaGetSymbolAddress((void**)&q,    g_q);
    cudaGetSymbolAddress((void**)&k,    g_k);
    cudaGetSymbolAddress((void**)&hx,   h_x);
    cudaGetSymbolAddress((void**)&hWq,  h_Wq);
    cudaGetSymbolAddress((void**)&hWkv, h_Wkv);
    cudaGetSymbolAddress((void**)&hWkrn, h_Wkrn);
    cudaGetSymbolAddress((void**)&hWv,  h_Wv);
    cudaGetSymbolAddress((void**)&hWo,  h_Wo);
    cudaGetSymbolAddress((void**)&hlat, h_lat);
    cudaGetSymbolAddress((void**)&hattn, h_attn);
    cudaGetSymbolAddress((void**)&hq,   h_q);
    cudaGetSymbolAddress((void**)&hk,   h_k);
    cudaGetSymbolAddress((void**)&hv,   h_v);

    dim3 blk(256);

    convert_all<<<CV_BLOCKS, blk>>>(x, Wq, Wkv, Wkr, Wkn, Wv, Wo,
                                    hx, hWq, hWkv, hWkrn, hWv, hWo);

    hgemm128<float, false><<<dim3(16, 32), blk>>>(hx, hWq, q, TOKS, 2048, HIDN,
                                                  11, 2048, 0, 2048);
    hgemm128<__half, false><<<dim3(4, 32), blk>>>(hx, hWkv, hlat, TOKS, DLAT, HIDN,
                                                  9, DLAT, 0, DLAT);
    hgemm128<float, false><<<dim3(16, 32), blk>>>(hlat, hWkrn, k, TOKS, 2048, DLAT,
                                                  11, 2048, 0, 2048);
    hgemm128<__half, true><<<dim3(16, 32), blk>>>(hlat, hWv, hv, TOKS, 2048, DLAT,
                                                  11, 2048, 0, 2048);

    rmsnorm_h<<<TOKS * NH / 8, blk>>>(q, gq, hq, 0.12751677572069723f, 0);
    rmsnorm_h<<<TOKS * NH / 8, blk>>>(k, gk, hk, 1.0f, 1);

    attn_mma<<<dim3(SEQ / 64, NB * NH), dim3(128)>>>(hq, hk, hv, hattn);

    hgemm128<float, false><<<dim3(16, 32), blk>>>(hattn, hWo, out, TOKS, 2048, 2048,
                                                  11, 2048, 0, 2048);
}

// round 17
// speedup vs baseline: 1.0164x; 1.0164x over previous
#include <cuda_runtime.h>
#include <cuda_fp16.h>
#include <math.h>
#include <stdint.h>

// Problem constants
#define TOKS 4096      // B*S = 2*2048
#define SEQ  2048
#define NB   2
#define NH   16
#define HD   128
#define HIDN 2048
#define DLAT 512

// fp32 scratch (GEMM outputs pre-norm)
__device__ float g_q[TOKS * 2048];
__device__ float g_k[TOKS * 2048];

// fp16 scratch
__device__ __half h_x[TOKS * HIDN];
__device__ __half h_Wq[HIDN * 2048];
__device__ __half h_Wkv[HIDN * DLAT];
__device__ __half h_Wkrn[DLAT * 2048];   // combined head-interleaved kr|kn weight
__device__ __half h_Wv[DLAT * 2048];
__device__ __half h_Wo[2048 * HIDN];
__device__ __half h_lat[TOKS * DLAT];
__device__ __half h_attn[TOKS * 2048];
__device__ __half h_k[TOKS * 2048];   // [b][h][s][d], XOR-swizzled rows
__device__ __half h_v[TOKS * 2048];   // [b][h][s][d], XOR-swizzled rows

// ----------------------------------------------------------------------------
// Fused fp32->fp16 conversion of x + all weights (Wkr/Wkn remap into h_Wkrn).
// ----------------------------------------------------------------------------
#define V4_X    2097152L
#define V4_WQ   1048576L
#define V4_WKV   262144L
#define V4_WKR   131072L
#define V4_WKN   131072L
#define V4_WV    262144L
#define V4_WO   1048576L
#define CV_B0 (V4_X)
#define CV_B1 (CV_B0 + V4_WQ)
#define CV_B2 (CV_B1 + V4_WKV)
#define CV_B3 (CV_B2 + V4_WKR)
#define CV_B4 (CV_B3 + V4_WKN)
#define CV_B5 (CV_B4 + V4_WV)
#define CV_B6 (CV_B5 + V4_WO)
#define CV_BLOCKS (CV_B6 / 256)

__device__ __forceinline__ void cvt4(const float* s, __half* d, long si, long di)
{
    float4 v = *(const float4*)(s + si * 4);
    *(__half2*)(d + di * 4)     = __floats2half2_rn(v.x, v.y);
    *(__half2*)(d + di * 4 + 2) = __floats2half2_rn(v.z, v.w);
}

__global__ __launch_bounds__(256)
void convert_all(const float* __restrict__ x,  const float* __restrict__ Wq,
                 const float* __restrict__ Wkv, const float* __restrict__ Wkr,
                 const float* __restrict__ Wkn, const float* __restrict__ Wv,
                 const float* __restrict__ Wo,
                 __half* __restrict__ hx,  __half* __restrict__ hWq,
                 __half* __restrict__ hWkv, __half* __restrict__ hWkrn,
                 __half* __restrict__ hWv, __half* __restrict__ hWo)
{
    long v4 = (long)blockIdx.x * 256 + threadIdx.x;
    if (v4 < CV_B0)      cvt4(x,   hx,   v4, v4);
    else if (v4 < CV_B1) cvt4(Wq,  hWq,  v4 - CV_B0, v4 - CV_B0);
    else if (v4 < CV_B2) cvt4(Wkv, hWkv, v4 - CV_B1, v4 - CV_B1);
    else if (v4 < CV_B3) {
        long e = v4 - CV_B2;
        long row = e >> 8;
        int j = (int)(e & 255) * 4;
        int h = j >> 6, c = j & 63;
        long dst = row * 2048 + h * 128 + c;
        cvt4(Wkr, hWkrn, e, dst >> 2);
    } else if (v4 < CV_B4) {
        long e = v4 - CV_B3;
        long row = e >> 8;
        int j = (int)(e & 255) * 4;
        int h = j >> 6, c = j & 63;
        long dst = row * 2048 + h * 128 + 64 + c;
        cvt4(Wkn, hWkrn, e, dst >> 2);
    }
    else if (v4 < CV_B5) cvt4(Wv, hWv, v4 - CV_B4, v4 - CV_B4);
    else                 cvt4(Wo, hWo, v4 - CV_B5, v4 - CV_B5);
}

// ----------------------------------------------------------------------------
#define AS_STRIDE 40
#define BS_STRIDE 136
#define A_STG (128 * AS_STRIDE)
#define B_STG (32 * BS_STRIDE)

__device__ __forceinline__ uint32_t sptr(const void* p)
{
    return (uint32_t)__cvta_generic_to_shared(p);
}
__device__ __forceinline__ void ldsm_x4(uint32_t* r, uint32_t addr)
{
    asm volatile("ldmatrix.sync.aligned.m8n8.x4.shared.b16 {%0,%1,%2,%3}, [%4];\n"
                 : "=r"(r[0]), "=r"(r[1]), "=r"(r[2]), "=r"(r[3]) : "r"(addr));
}
__device__ __forceinline__ void ldsm_x2t(uint32_t* r, uint32_t addr)
{
    asm volatile("ldmatrix.sync.aligned.m8n8.x2.trans.shared.b16 {%0,%1}, [%2];\n"
                 : "=r"(r[0]), "=r"(r[1]) : "r"(addr));
}
__device__ __forceinline__ void ldsm_x4t(uint32_t* r, uint32_t addr)
{
    asm volatile("ldmatrix.sync.aligned.m8n8.x4.trans.shared.b16 {%0,%1,%2,%3}, [%4];\n"
                 : "=r"(r[0]), "=r"(r[1]), "=r"(r[2]), "=r"(r[3]) : "r"(addr));
}
__device__ __forceinline__ void mma16816(float* c, const uint32_t* a, const uint32_t* b)
{
    asm volatile(
        "mma.sync.aligned.m16n8k16.row.col.f32.f16.f16.f32 "
        "{%0,%1,%2,%3}, {%4,%5,%6,%7}, {%8,%9}, {%0,%1,%2,%3};\n"
        : "+f"(c[0]), "+f"(c[1]), "+f"(c[2]), "+f"(c[3])
        : "r"(a[0]), "r"(a[1]), "r"(a[2]), "r"(a[3]), "r"(b[0]), "r"(b[1]));
}
__device__ __forceinline__ void cp16(uint32_t saddr, const void* g)
{
    asm volatile("cp.async.cg.shared.global [%0], [%1], 16;\n" :: "r"(saddr), "l"(g));
}
__device__ __forceinline__ void cp_commit()
{
    asm volatile("cp.async.commit_group;\n");
}
template <int N>
__device__ __forceinline__ void cp_wait()
{
    asm volatile("cp.async.wait_group %0;\n" :: "n"(N));
}
__device__ __forceinline__ float fast_ex2(float x)
{
    float y;
    asm("ex2.approx.ftz.f32 %0, %1;\n" : "=f"(y) : "f"(x));
    return y;
}
// mbarrier helpers
__device__ __forceinline__ void mbar_init(uint32_t addr, uint32_t count)
{
    asm volatile("mbarrier.init.shared.b64 [%0], %1;\n" :: "r"(addr), "r"(count) : "memory");
}
__device__ __forceinline__ void mbar_expect_tx(uint32_t addr, uint32_t bytes)
{
    asm volatile("mbarrier.arrive.expect_tx.shared.b64 _, [%0], %1;\n"
                 :: "r"(addr), "r"(bytes) : "memory");
}
__device__ __forceinline__ void mbar_wait(uint32_t addr, uint32_t parity)
{
    asm volatile(
        "{\n\t.reg .pred P;\n"
        "WAIT_%=:\n\t"
        "mbarrier.try_wait.parity.acquire.cta.shared::cta.b64 P, [%0], %1;\n\t"
        "@!P bra WAIT_%=;\n\t}"
        :: "r"(addr), "r"(parity) : "memory");
}
__device__ __forceinline__ void bulk_g2s(uint32_t dst, const void* src, uint32_t bytes,
                                         uint32_t mbar)
{
    asm volatile(
        "cp.async.bulk.shared::cta.global.mbarrier::complete_tx::bytes [%0], [%1], %2, [%3];\n"
        :: "r"(dst), "l"(src), "r"(bytes), "r"(mbar) : "memory");
}

// ----------------------------------------------------------------------------
// Tensor-core GEMM. SWZV: store fp16 output in [b][h][s][d] XOR-swizzled.
// ----------------------------------------------------------------------------
template <typename T, bool SWZV>
__global__ __launch_bounds__(256, 2)
void hgemm128(const __half* __restrict__ A, const __half* __restrict__ B,
              T* __restrict__ C, int M, int N, int K,
              int lgGroup, int outstride, int base, int ldc)
{
    __shared__ __half Asb[2 * A_STG];
    __shared__ __half Bsb[2 * B_STG];

    const int tid  = threadIdx.x;
    const int warp = tid >> 5;
    const int lane = tid & 31;
    const int bm = blockIdx.y * 128;
    const int bn = blockIdx.x * 128;
    const int wm = (warp & 1) * 64;
    const int wn = (warp >> 1) * 32;

    float c[4][4][4];
#pragma unroll
    for (int mt = 0; mt < 4; ++mt)
#pragma unroll
        for (int nt = 0; nt < 4; ++nt)
#pragma unroll
            for (int i = 0; i < 4; ++i) c[mt][nt][i] = 0.0f;

    const int arow0 = tid >> 2,  akc = (tid & 3) * 8;
    const int brow0 = tid >> 4,  bnc = (tid & 15) * 8;

    const uint32_t a_base = sptr(&Asb[(wm + (lane & 15)) * AS_STRIDE + (lane >> 4) * 8]);
    const uint32_t b_base = sptr(&Bsb[(lane & 15) * BS_STRIDE + wn]);

    const int nk = K >> 5;

#define GEMM_LOAD_STAGE(s, k0)                                                        \
    do {                                                                              \
        cp16(sptr(&Asb[(s) * A_STG + arow0 * AS_STRIDE + akc]),                       \
             A + (size_t)(bm + arow0) * K + (k0) + akc);                              \
        cp16(sptr(&Asb[(s) * A_STG + (arow0 + 64) * AS_STRIDE + akc]),                \
             A + (size_t)(bm + arow0 + 64) * K + (k0) + akc);                         \
        cp16(sptr(&Bsb[(s) * B_STG + brow0 * BS_STRIDE + bnc]),                       \
             B + (size_t)((k0) + brow0) * N + bn + bnc);                              \
        cp16(sptr(&Bsb[(s) * B_STG + (brow0 + 16) * BS_STRIDE + bnc]),                \
             B + (size_t)((k0) + brow0 + 16) * N + bn + bnc);                         \
    } while (0)

    GEMM_LOAD_STAGE(0, 0);
    cp_commit();

    for (int t = 0; t < nk; ++t) {
        cp_wait<0>();
        __syncthreads();
        if (t + 1 < nk) {
            GEMM_LOAD_STAGE((t + 1) & 1, (t + 1) << 5);
            cp_commit();
        }

        const uint32_t ab = a_base + (t & 1) * A_STG * 2;
        const uint32_t bb = b_base + (t & 1) * B_STG * 2;
#pragma unroll
        for (int kt = 0; kt < 2; ++kt) {
            uint32_t a[4][4], b[4][2];
#pragma unroll
            for (int mt = 0; mt < 4; ++mt)
                ldsm_x4(a[mt], ab + (mt * 16 * AS_STRIDE + kt * 16) * 2);
#pragma unroll
            for (int nt = 0; nt < 4; ++nt)
                ldsm_x2t(b[nt], bb + (kt * 16 * BS_STRIDE + nt * 8) * 2);
#pragma unroll
            for (int mt = 0; mt < 4; ++mt)
#pragma unroll
                for (int nt = 0; nt < 4; ++nt)
                    mma16816(c[mt][nt], a[mt], b[nt]);
        }
    }

    const int gmask = (1 << lgGroup) - 1;
    const int gid = lane >> 2;
    const int tig = lane & 3;
#pragma unroll
    for (int mt = 0; mt < 4; ++mt) {
#pragma unroll
        for (int nt = 0; nt < 4; ++nt) {
            int col = bn + wn + nt * 8 + tig * 2;
            int oc = ((col >> lgGroup) * outstride) + base + (col & gmask);
            int r0 = bm + wm + mt * 16 + gid;
            if (sizeof(T) == 4) {
                *(float2*)&((float*)C)[(size_t)r0 * ldc + oc] =
                    make_float2(c[mt][nt][0], c[mt][nt][1]);
                *(float2*)&((float*)C)[(size_t)(r0 + 8) * ldc + oc] =
                    make_float2(c[mt][nt][2], c[mt][nt][3]);
            } else if (SWZV) {
                int hh = oc >> 7, d = oc & 127;
#pragma unroll
                for (int rr = 0; rr < 2; ++rr) {
                    int tok = r0 + rr * 8;
                    int bb2 = tok >> 11, ss = tok & 2047;
                    size_t rb = ((size_t)(bb2 * 16 + hh) * 2048 + ss) * 128;
                    int dd = (((d >> 3) ^ (ss & 7)) << 3) + (d & 7);
                    *(__half2*)&((__half*)C)[rb + dd] =
                        __floats2half2_rn(c[mt][nt][rr * 2], c[mt][nt][rr * 2 + 1]);
                }
            } else {
                *(__half2*)&((__half*)C)[(size_t)r0 * ldc + oc] =
                    __floats2half2_rn(c[mt][nt][0], c[mt][nt][1]);
                *(__half2*)&((__half*)C)[(size_t)(r0 + 8) * ldc + oc] =
                    __floats2half2_rn(c[mt][nt][2], c[mt][nt][3]);
            }
        }
    }
}

// ----------------------------------------------------------------------------
// RMSNorm + fp16 repack -> [b][h][s][d] with 16B-chunk XOR swizzle (K only).
// ----------------------------------------------------------------------------
__global__ __launch_bounds__(256)
void rmsnorm_h(const float* __restrict__ in, const float* __restrict__ g,
               __half* __restrict__ out, float pscale, int swz)
{
    int row = blockIdx.x * 8 + (threadIdx.x >> 5);   // row = tok*16 + h
    int lane = threadIdx.x & 31;
    float4 v = *((const float4*)(in + (size_t)row * 128) + lane);
    float ss = v.x * v.x + v.y * v.y + v.z * v.z + v.w * v.w;
#pragma unroll
    for (int o = 16; o; o >>= 1) ss += __shfl_xor_sync(0xffffffffu, ss, o);
    float r = rsqrtf(ss * (1.0f / 128.0f) + 1e-6f) * pscale;
    float4 gv = ((const float4*)g)[lane];
    int tok = row >> 4, h = row & 15;
    int b = tok >> 11, s = tok & 2047;
    int xs = swz ? (s & 7) : 0;
    int dd = (((lane >> 1) ^ xs) << 3) + (lane & 1) * 4;
    __half* dst = out + ((size_t)(b * 16 + h) * 2048 + s) * 128 + dd;
    *(__half2*)dst       = __floats2half2_rn(v.x * r * gv.x, v.y * r * gv.y);
    *(__half2*)(dst + 2) = __floats2half2_rn(v.z * r * gv.z, v.w * r * gv.w);
}

// ----------------------------------------------------------------------------
// Tensor-core causal flash attention: 32-key tiles, double-buffered combined
// K+V stages (bulk copies, R15 structure), fused in-kernel Q RMSNorm
// (reads fp32 q, applies gq * log2e/sqrt(D)), split QK accumulator chains
// (8 chains of depth 4). Fixed-shift MUFU softmax. 128 thr / 64 q / 3 CTA-SM.
// ----------------------------------------------------------------------------
#define SOFTMAX_SHIFT 2.8853900817779268f   /* 2*log2e */
#define QSCALE 0.12751677572069723f         /* log2e / sqrt(128) */
#define STG_BYTES 16384u
#define KTILE_B 8192u

__global__ __launch_bounds__(128, 3)
void attn_mma(const float* __restrict__ qf, const float* __restrict__ gqv,
              const __half* __restrict__ k, const __half* __restrict__ v,
              __half* __restrict__ o)
{
    __shared__ __align__(128) __half KV[2][8192];         // 2 stages x 16KB
    __shared__ __align__(8) unsigned long long mbar[2];

    const int bh = blockIdx.y;
    const int b = bh >> 4, h = bh & 15;
    const int qb = ((int)gridDim.x - 1 - (int)blockIdx.x) * 64;   // heavy first
    const int tid = threadIdx.x;
    const int lane = tid & 31;
    const int warp = tid >> 5;
    const size_t base = (size_t)bh * SEQ * HD;
    const int r0 = warp * 16 + (lane >> 2);
    const int w0 = qb + warp * 16;
    const int c2 = (lane & 3) * 2;

    const uint32_t mb0 = sptr(&mbar[0]);
    const uint32_t smem0 = sptr(KV);

    const __half* kg = k + base;
    const __half* vg = v + base;
    const int ntiles = qb / 32 + 2;

    if (tid == 0) {
        mbar_init(mb0, 1);
        mbar_init(mb0 + 8, 1);
    }
    __syncthreads();
    if (tid == 0) {
        mbar_expect_tx(mb0, STG_BYTES);
        bulk_g2s(smem0, kg, KTILE_B, mb0);
        bulk_g2s(smem0 + KTILE_B, vg, KTILE_B, mb0);
        mbar_expect_tx(mb0 + 8, STG_BYTES);
        bulk_g2s(smem0 + STG_BYTES, kg + 4096, KTILE_B, mb0 + 8);
        bulk_g2s(smem0 + STG_BYTES + KTILE_B, vg + 4096, KTILE_B, mb0 + 8);
    }

    // --- fused Q RMSNorm: fp32 rows -> fp16 a-frags (overlaps first copies) ---
    uint32_t aq[8][4];
    {
        const float* f0 = qf + ((size_t)(b * SEQ + qb + r0) << 11) + (h << 7);
        const float* f1 = f0 + (8 << 11);
        float ss0 = 0.0f, ss1 = 0.0f;
#pragma unroll
        for (int kc = 0; kc < 8; ++kc) {
            float2 x0 = *(const float2*)(f0 + kc * 16 + c2);
            float2 x1 = *(const float2*)(f0 + kc * 16 + 8 + c2);
            float2 y0 = *(const float2*)(f1 + kc * 16 + c2);
            float2 y1 = *(const float2*)(f1 + kc * 16 + 8 + c2);
            ss0 += x0.x * x0.x + x0.y * x0.y + x1.x * x1.x + x1.y * x1.y;
            ss1 += y0.x * y0.x + y0.y * y0.y + y1.x * y1.x + y1.y * y1.y;
        }
        ss0 += __shfl_xor_sync(0xffffffffu, ss0, 1);
        ss0 += __shfl_xor_sync(0xffffffffu, ss0, 2);
        ss1 += __shfl_xor_sync(0xffffffffu, ss1, 1);
        ss1 += __shfl_xor_sync(0xffffffffu, ss1, 2);
        float ra = rsqrtf(ss0 * (1.0f / 128.0f) + 1e-6f) * QSCALE;
        float rb = rsqrtf(ss1 * (1.0f / 128.0f) + 1e-6f) * QSCALE;
#pragma unroll
        for (int kc = 0; kc < 8; ++kc) {
            float2 g0 = *(const float2*)(gqv + kc * 16 + c2);
            float2 g1 = *(const float2*)(gqv + kc * 16 + 8 + c2);
            float2 x0 = *(const float2*)(f0 + kc * 16 + c2);
            float2 x1 = *(const float2*)(f0 + kc * 16 + 8 + c2);
            float2 y0 = *(const float2*)(f1 + kc * 16 + c2);
            float2 y1 = *(const float2*)(f1 + kc * 16 + 8 + c2);
            __half2 h0 = __floats2half2_rn(x0.x * ra * g0.x, x0.y * ra * g0.y);
            __half2 h1 = __floats2half2_rn(y0.x * rb * g0.x, y0.y * rb * g0.y);
            __half2 h2 = __floats2half2_rn(x1.x * ra * g1.x, x1.y * ra * g1.y);
            __half2 h3 = __floats2half2_rn(y1.x * rb * g1.x, y1.y * rb * g1.y);
            aq[kc][0] = *(uint32_t*)&h0;
            aq[kc][1] = *(uint32_t*)&h1;
            aq[kc][2] = *(uint32_t*)&h2;
            aq[kc][3] = *(uint32_t*)&h3;
        }
    }

    float oa[16][4];
#pragma unroll
    for (int nt = 0; nt < 16; ++nt)
#pragma unroll
        for (int i = 0; i < 4; ++i) oa[nt][i] = 0.0f;
    float l0 = 0.0f, l1 = 0.0f;

    // swizzled ldsm lane addressing
    const uint32_t krow = (lane & 7) * 256;
    uint32_t kx[4];
#pragma unroll
    for (int g = 0; g < 4; ++g)
        kx[g] = ((((lane >> 3) + g * 4) ^ (lane & 7)) << 4);
    const uint32_t vrow = (lane & 15) * 256;
    uint32_t vx[8];
#pragma unroll
    for (int ntp = 0; ntp < 8; ++ntp)
        vx[ntp] = ((((lane >> 4) + ntp * 2) ^ (lane & 7)) << 4);

    for (int t = 0; t < ntiles; ++t) {
        const int j0 = t * 32;
        const int stg = t & 1;
        const uint32_t kbase = smem0 + stg * STG_BYTES;
        const uint32_t vbase = kbase + KTILE_B;

        mbar_wait(mb0 + stg * 8, (t >> 1) & 1);

        if (j0 <= w0 + 15) {                       // tile live for this warp
            // S = Q K^T  (32 keys), split accumulator chains
            float s[4][4];
#pragma unroll
            for (int nt = 0; nt < 4; ++nt) {
                float t2[4] = {0.0f, 0.0f, 0.0f, 0.0f};
                s[nt][0] = s[nt][1] = s[nt][2] = s[nt][3] = 0.0f;
                uint32_t bk[4][4];
#pragma unroll
                for (int g = 0; g < 4; ++g)
                    ldsm_x4(bk[g], kbase + krow + nt * 2048 + kx[g]);
#pragma unroll
                for (int kc = 0; kc < 4; ++kc)
                    mma16816(s[nt], aq[kc], &bk[kc >> 1][(kc & 1) * 2]);
#pragma unroll
                for (int kc = 4; kc < 8; ++kc)
                    mma16816(t2, aq[kc], &bk[kc >> 1][(kc & 1) * 2]);
                s[nt][0] += t2[0]; s[nt][1] += t2[1];
                s[nt][2] += t2[2]; s[nt][3] += t2[3];
            }

            if (j0 + 31 > w0) {                    // diagonal masking
#pragma unroll
                for (int nt = 0; nt < 4; ++nt) {
#pragma unroll
                    for (int i = 0; i < 4; ++i) {
                        int col = j0 + nt * 8 + c2 + (i & 1);
                        int rowq = qb + r0 + (i >> 1) * 8;
                        if (col > rowq) s[nt][i] = -1e30f;
                    }
                }
            }

            // fixed-shift MUFU exp2
#pragma unroll
            for (int nt = 0; nt < 4; ++nt) {
                s[nt][0] = fast_ex2(s[nt][0] - SOFTMAX_SHIFT);
                s[nt][1] = fast_ex2(s[nt][1] - SOFTMAX_SHIFT);
                s[nt][2] = fast_ex2(s[nt][2] - SOFTMAX_SHIFT);
                s[nt][3] = fast_ex2(s[nt][3] - SOFTMAX_SHIFT);
                l0 += s[nt][0] + s[nt][1];
                l1 += s[nt][2] + s[nt][3];
            }

            // pack P -> fp16 a-frags
            uint32_t ap[2][4];
#pragma unroll
            for (int kc = 0; kc < 2; ++kc) {
                __half2 t0 = __floats2half2_rn(s[2 * kc][0], s[2 * kc][1]);
                __half2 t1 = __floats2half2_rn(s[2 * kc][2], s[2 * kc][3]);
                __half2 t2h = __floats2half2_rn(s[2 * kc + 1][0], s[2 * kc + 1][1]);
                __half2 t3 = __floats2half2_rn(s[2 * kc + 1][2], s[2 * kc + 1][3]);
                ap[kc][0] = *(uint32_t*)&t0;
                ap[kc][1] = *(uint32_t*)&t1;
                ap[kc][2] = *(uint32_t*)&t2h;
                ap[kc][3] = *(uint32_t*)&t3;
            }

            // O += P V
#pragma unroll
            for (int kc = 0; kc < 2; ++kc) {
#pragma unroll
                for (int ntp = 0; ntp < 8; ++ntp) {
                    uint32_t bv[4];
                    ldsm_x4t(bv, vbase + vrow + kc * 4096 + vx[ntp]);
                    mma16816(oa[ntp * 2], ap[kc], &bv[0]);
                    mma16816(oa[ntp * 2 + 1], ap[kc], &bv[2]);
                }
            }
        }

        __syncthreads();          // stage (t&1) free for reuse
        if (tid == 0 && t + 2 < ntiles) {
            const __half* kg2 = kg + (size_t)(t + 2) * 4096;
            const __half* vg2 = vg + (size_t)(t + 2) * 4096;
            mbar_expect_tx(mb0 + stg * 8, STG_BYTES);
            bulk_g2s(kbase, kg2, KTILE_B, mb0 + stg * 8);
            bulk_g2s(vbase, vg2, KTILE_B, mb0 + stg * 8);
        }
    }

    // row-sum reduction of l (4 lanes per row), then normalize
    l0 += __shfl_xor_sync(0xffffffffu, l0, 1);
    l0 += __shfl_xor_sync(0xffffffffu, l0, 2);
    l1 += __shfl_xor_sync(0xffffffffu, l1, 1);
    l1 += __shfl_xor_sync(0xffffffffu, l1, 2);
    float inv0 = 1.0f / l0, inv1 = 1.0f / l1;
    size_t tok0 = (size_t)b * SEQ + qb + r0;
    __half* d0 = o + tok0 * 2048 + h * 128 + c2;
    __half* d1 = d0 + (size_t)8 * 2048;
#pragma unroll
    for (int nt = 0; nt < 16; ++nt) {
        *(__half2*)(d0 + nt * 8) = __floats2half2_rn(oa[nt][0] * inv0, oa[nt][1] * inv0);
        *(__half2*)(d1 + nt * 8) = __floats2half2_rn(oa[nt][2] * inv1, oa[nt][3] * inv1);
    }
}

// ----------------------------------------------------------------------------
extern "C" void kernel_launch(void* const* d_in, const int* in_sizes, int n_in,
                              void* d_out, int out_size)
{
    const float* x   = (const float*)d_in[0];
    const float* Wq  = (const float*)d_in[1];
    const float* Wkv = (const float*)d_in[2];
    const float* Wkr = (const float*)d_in[3];
    const float* Wkn = (const float*)d_in[4];
    const float* Wv  = (const float*)d_in[5];
    const float* Wo  = (const float*)d_in[6];
    const float* gq  = (const float*)d_in[7];
    const float* gk  = (const float*)d_in[8];
    float* out = (float*)d_out;

    float *q, *k;
    __half *hx, *hWq, *hWkv, *hWkrn, *hWv, *hWo, *hlat, *hattn, *hk, *hv;
    cudaGetSymbolAddress((void**)&q,    g_q);
    cudaGetSymbolAddress((void**)&k,    g_k);
    cudaGetSymbolAddress((void**)&hx,   h_x);
    cudaGetSymbolAddress((void**)&hWq,  h_Wq);
    cudaGetSymbolAddress((void**)&hWkv, h_Wkv);
    cudaGetSymbolAddress((void**)&hWkrn, h_Wkrn);
    cudaGetSymbolAddress((void**)&hWv,  h_Wv);
    cudaGetSymbolAddress((void**)&hWo,  h_Wo);
    cudaGetSymbolAddress((void**)&hlat, h_lat);
    cudaGetSymbolAddress((void**)&hattn, h_attn);
    cudaGetSymbolAddress((void**)&hk,   h_k);
    cudaGetSymbolAddress((void**)&hv,   h_v);

    dim3 blk(256);

    convert_all<<<CV_BLOCKS, blk>>>(x, Wq, Wkv, Wkr, Wkn, Wv, Wo,
                                    hx, hWq, hWkv, hWkrn, hWv, hWo);

    hgemm128<float, false><<<dim3(16, 32), blk>>>(hx, hWq, q, TOKS, 2048, HIDN,
                                                  11, 2048, 0, 2048);
    hgemm128<__half, false><<<dim3(4, 32), blk>>>(hx, hWkv, hlat, TOKS, DLAT, HIDN,
                                                  9, DLAT, 0, DLAT);
    hgemm128<float, false><<<dim3(16, 32), blk>>>(hlat, hWkrn, k, TOKS, 2048, DLAT,
                                                  11, 2048, 0, 2048);
    hgemm128<__half, true><<<dim3(16, 32), blk>>>(hlat, hWv, hv, TOKS, 2048, DLAT,
                                                  11, 2048, 0, 2048);

    // K norm + swizzled repack (Q norm is fused into attention)
    rmsnorm_h<<<TOKS * NH / 8, blk>>>(k, gk, hk, 1.0f, 1);

    attn_mma<<<dim3(SEQ / 64, NB * NH), dim3(128)>>>(q, gq, hk, hv, hattn);

    hgemm128<float, false><<<dim3(16, 32), blk>>>(hattn, hWo, out, TOKS, 2048, 2048,
                                                  11, 2048, 0, 2048);
}